// round 7
// baseline (speedup 1.0000x reference)
#include <cuda_runtime.h>
#include <math.h>
#include <stdint.h>

#define T_STEPS 512
#define BATCH   64
#define IN_DIM  256
#define HID     512
#define OUT_DIM 256
#define BH      (BATCH * HID)        // 32768
#define M_ROWS  (T_STEPS * BATCH)    // 32768

// Scratch (allocation-free rule: __device__ globals)
__device__ float g_xp[(size_t)M_ROWS * HID];   // xp = x@W_ih^T + b_ih + b_hh
__device__ float g_rnn[(size_t)M_ROWS * HID];  // rnn_out (h history)

// fast tanh: rel err ~1e-6, clamped (no NaN)
__device__ __forceinline__ float tanh_fast(float x) {
    float xc = fminf(9.0f, fmaxf(-9.0f, x));
    float e  = exp2f(2.885390081777927f * xc);   // e^(2x)
    return __fdividef(e - 1.0f, e + 1.0f);
}

// -------------------- SGEMM: C[M,N] = A[M,K] @ Bw[N,K]^T + bias --------------------
template<int BM, int BN, int BK, int TM, int TN, int THREADS>
__global__ __launch_bounds__(THREADS)
void sgemm_bt_bias(const float* __restrict__ A,
                   const float* __restrict__ Bw,
                   const float* __restrict__ bias0,
                   const float* __restrict__ bias1,
                   float* __restrict__ C,
                   int M, int N, int K)
{
    __shared__ float As[BK][BM];
    __shared__ float Bs[BK][BN];

    const int tid = threadIdx.x;
    const int tx  = tid % (BN / TN);
    const int ty  = tid / (BN / TN);
    const int m0  = blockIdx.y * BM;
    const int n0  = blockIdx.x * BN;

    float acc[TM][TN];
    #pragma unroll
    for (int i = 0; i < TM; ++i)
        #pragma unroll
        for (int j = 0; j < TN; ++j) acc[i][j] = 0.f;

    for (int k0 = 0; k0 < K; k0 += BK) {
        #pragma unroll
        for (int i = tid; i < (BM * BK) / 4; i += THREADS) {
            int r  = i / (BK / 4);
            int c4 = i % (BK / 4);
            float4 v = *(const float4*)&A[(size_t)(m0 + r) * K + k0 + c4 * 4];
            As[c4 * 4 + 0][r] = v.x;
            As[c4 * 4 + 1][r] = v.y;
            As[c4 * 4 + 2][r] = v.z;
            As[c4 * 4 + 3][r] = v.w;
        }
        #pragma unroll
        for (int i = tid; i < (BN * BK) / 4; i += THREADS) {
            int r  = i / (BK / 4);
            int c4 = i % (BK / 4);
            float4 v = *(const float4*)&Bw[(size_t)(n0 + r) * K + k0 + c4 * 4];
            Bs[c4 * 4 + 0][r] = v.x;
            Bs[c4 * 4 + 1][r] = v.y;
            Bs[c4 * 4 + 2][r] = v.z;
            Bs[c4 * 4 + 3][r] = v.w;
        }
        __syncthreads();

        #pragma unroll
        for (int kk = 0; kk < BK; ++kk) {
            float aR[TM], bR[TN];
            #pragma unroll
            for (int i = 0; i < TM; ++i) aR[i] = As[kk][ty * TM + i];
            #pragma unroll
            for (int j = 0; j < TN; ++j) bR[j] = Bs[kk][tx * TN + j];
            #pragma unroll
            for (int i = 0; i < TM; ++i)
                #pragma unroll
                for (int j = 0; j < TN; ++j)
                    acc[i][j] += aR[i] * bR[j];
        }
        __syncthreads();
    }

    float bj[TN];
    #pragma unroll
    for (int j = 0; j < TN; ++j) {
        int n = n0 + tx * TN + j;
        bj[j] = bias0[n] + (bias1 ? bias1[n] : 0.f);
    }
    #pragma unroll
    for (int i = 0; i < TM; ++i) {
        int m = m0 + ty * TM + i;
        #pragma unroll
        for (int j = 0; j < TN; ++j) {
            int n = n0 + tx * TN + j;
            C[(size_t)m * N + n] = acc[i][j] + bj[j];
        }
    }
}

// -------------------- recurrent scan v5: clusters + DSMEM exchange --------------------
// 128 CTAs = 16 clusters (batch groups of 4) x 8 CTAs (col groups of 64).
// No global barrier: h exchanged via st.shared::cluster into peers' ping-pong sH,
// synced with barrier.cluster. g_rnn history store is fire-and-forget.
#define CLUSTER_N 8
#define COLS_CTA  64
#define BPG       4            // batches per cluster
#define WS        516          // sW row stride (floats)
#define HS        520          // sH row stride (floats)
#define SW_FLOATS (COLS_CTA * WS)          // 33024
#define SH_FLOATS (2 * BPG * HS)           // 4160 (ping-pong)
#define SC_FLOATS (BPG * COLS_CTA)         // 256 scratch chunk
#define SMEM_SCAN_BYTES ((SW_FLOATS + SH_FLOATS + SC_FLOATS) * 4)   // 149760

__device__ __forceinline__ uint32_t smem_u32(const void* p) {
    uint32_t a;
    asm("{ .reg .u64 t; cvta.to.shared.u64 t, %1; cvt.u32.u64 %0, t; }"
        : "=r"(a) : "l"(p));
    return a;
}
__device__ __forceinline__ uint32_t mapa32(uint32_t addr, int rank) {
    uint32_t r;
    asm("mapa.shared::cluster.u32 %0, %1, %2;" : "=r"(r) : "r"(addr), "r"(rank));
    return r;
}
__device__ __forceinline__ void st_cluster_v4(uint32_t addr, float4 v) {
    asm volatile("st.shared::cluster.v4.f32 [%0], {%1,%2,%3,%4};"
                 :: "r"(addr), "f"(v.x), "f"(v.y), "f"(v.z), "f"(v.w) : "memory");
}
__device__ __forceinline__ void st_shared_v4(uint32_t addr, float4 v) {
    asm volatile("st.shared.v4.f32 [%0], {%1,%2,%3,%4};"
                 :: "r"(addr), "f"(v.x), "f"(v.y), "f"(v.z), "f"(v.w) : "memory");
}
__device__ __forceinline__ void cluster_sync_() {
    asm volatile("barrier.cluster.arrive.aligned;" ::: "memory");
    asm volatile("barrier.cluster.wait.aligned;" ::: "memory");
}

__global__ __launch_bounds__(256, 1) __cluster_dims__(CLUSTER_N, 1, 1)
void rnn_scan5(const float* __restrict__ Whh,   // [HID, HID]
               float* __restrict__ h_out)       // [BATCH, HID]
{
    extern __shared__ float sm[];
    float* sW = sm;                     // [64][WS]
    float* sH = sm + SW_FLOATS;         // [2][BPG][HS]
    float* sC = sH + SH_FLOATS;         // [BPG][64]

    const int tid  = threadIdx.x;
    const int g    = blockIdx.x >> 3;   // batch group 0..15
    const int rank = blockIdx.x & 7;    // col group within cluster
    const int w = tid >> 5, l = tid & 31;
    const int bl   = l >> 3;                 // 0..3
    const int c    = w * 8 + (l & 7);        // 0..63
    const int colg = rank * COLS_CTA + c;
    const int b    = g * BPG + bl;

    // load W_hh rows [rank*64, +64) into SMEM
    for (int i = tid; i < COLS_CTA * (HID / 4); i += 256) {
        int r  = i >> 7;
        int k4 = i & 127;
        float4 v = *(const float4*)&Whh[(size_t)(rank * COLS_CTA + r) * HID + k4 * 4];
        *(float4*)&sW[r * WS + k4 * 4] = v;
    }

    // peer sH base addresses (same smem layout in every CTA)
    const uint32_t sh_local = smem_u32(sH);
    uint32_t peer[CLUSTER_N];
    #pragma unroll
    for (int r = 0; r < CLUSTER_N; ++r)
        peer[r] = (r == rank) ? sh_local : mapa32(sh_local, r);

    __syncthreads();

    float my_xp = g_xp[(size_t)b * HID + colg];   // t = 0

    const ulonglong2* w2 = (const ulonglong2*)&sW[c * WS];

    for (int t = 0; t < T_STEPS; ++t) {
        const int pc = t & 1;            // buffer produced this step
        float acc = my_xp;
        if (t > 0) {
            const ulonglong2* h2 = (const ulonglong2*)&sH[(pc ^ 1) * (BPG * HS) + bl * HS];
            unsigned long long a01 = 0ull, a23 = 0ull;
            #pragma unroll 8
            for (int k4 = 0; k4 < HID / 4; ++k4) {
                ulonglong2 hv = h2[k4];
                ulonglong2 wv = w2[k4];
                asm("fma.rn.f32x2 %0, %1, %2, %0;" : "+l"(a01) : "l"(hv.x), "l"(wv.x));
                asm("fma.rn.f32x2 %0, %1, %2, %0;" : "+l"(a23) : "l"(hv.y), "l"(wv.y));
            }
            float s0, s1, s2, s3;
            asm("mov.b64 {%0, %1}, %2;" : "=f"(s0), "=f"(s1) : "l"(a01));
            asm("mov.b64 {%0, %1}, %2;" : "=f"(s2), "=f"(s3) : "l"(a23));
            acc += (s0 + s1) + (s2 + s3);
        }
        float hn = tanh_fast(acc);
        sC[bl * COLS_CTA + c] = hn;
        if (t + 1 < T_STEPS)
            my_xp = g_xp[(size_t)(t + 1) * BH + (size_t)b * HID + colg];  // prefetch

        if (t == T_STEPS - 1) {
            // final step (uniform across cluster): no exchange needed
            g_rnn[(size_t)t * BH + (size_t)b * HID + colg] = hn;
            h_out[(size_t)b * HID + colg] = hn;
            break;
        }

        __syncthreads();   // sC complete

        // push chunk to all 8 CTAs' sH[pc] + fire-and-forget g_rnn store
        // u in [0,512): DSMEM/local SMEM pushes; u in [512,576): gmem history
        for (int u = tid; u < 512 + 64; u += 256) {
            int rem = u & 63;
            int row = rem >> 4;       // bl
            int f4  = rem & 15;
            float4 v = *(float4*)&sC[row * COLS_CTA + f4 * 4];
            if (u < 512) {
                int r = u >> 6;       // target rank
                uint32_t a = peer[r] +
                    (uint32_t)(((pc * BPG + row) * HS + rank * COLS_CTA + f4 * 4) * 4);
                if (r == rank) st_shared_v4(a, v);
                else           st_cluster_v4(a, v);
            } else {
                *(float4*)&g_rnn[(size_t)t * BH + (size_t)(g * BPG + row) * HID
                                 + rank * COLS_CTA + f4 * 4] = v;
            }
        }

        cluster_sync_();   // release my DSMEM writes / acquire peers'; also block-syncs
    }
}

__global__ void dummy_k() {}

// -------------------- launch --------------------
extern "C" void kernel_launch(void* const* d_in, const int* in_sizes, int n_in,
                              void* d_out, int out_size)
{
    const float* x     = (const float*)d_in[0];
    const float* W_ih  = (const float*)d_in[1];
    const float* W_hh  = (const float*)d_in[2];
    const float* b_ih  = (const float*)d_in[3];
    const float* b_hh  = (const float*)d_in[4];
    const float* W_out = (const float*)d_in[5];
    const float* b_out = (const float*)d_in[6];

    float* y = (float*)d_out;                             // [T,B,O]
    float* h = y + (size_t)T_STEPS * BATCH * OUT_DIM;     // [1,B,H]

    float* xp  = nullptr;
    float* rnn = nullptr;
    cudaGetSymbolAddress((void**)&xp,  g_xp);
    cudaGetSymbolAddress((void**)&rnn, g_rnn);

    // K1: xp = x @ W_ih^T + b_ih + b_hh    (M=32768, N=512, K=256)
    {
        dim3 grid(HID / 64, M_ROWS / 128);
        sgemm_bt_bias<128, 64, 16, 8, 4, 256><<<grid, 256>>>(
            x, W_ih, b_ih, b_hh, xp, M_ROWS, HID, IN_DIM);
    }

    // two dummies so the scan sits at global launch #6 for ncu (-s 5 -c 1)
    dummy_k<<<1, 32>>>();
    dummy_k<<<1, 32>>>();

    // K2: clustered recurrence; writes g_rnn + h_last
    cudaFuncSetAttribute(rnn_scan5, cudaFuncAttributeMaxDynamicSharedMemorySize,
                         SMEM_SCAN_BYTES);
    rnn_scan5<<<128, 256, SMEM_SCAN_BYTES>>>(W_hh, h);

    // K3: y = rnn_out @ W_out^T + b_out    (M=32768, N=256, K=512)
    {
        dim3 grid(OUT_DIM / 64, M_ROWS / 128);
        sgemm_bt_bias<128, 64, 16, 8, 4, 256><<<grid, 256>>>(
            rnn, W_out, b_out, nullptr, y, M_ROWS, OUT_DIM, HID);
    }
}